// round 15
// baseline (speedup 1.0000x reference)
#include <cuda_runtime.h>
#include <cstdint>
#include <cstring>

#define SQ 512
#define BB 64
#define EE 128
#define HH 256
#define NG 1024   // 4*H

// ---------------- scratch (static device memory; no allocations) ----------------
__device__ float g_x [SQ*BB*EE];          // embedded inputs          16 MB
__device__ float g_xg[(size_t)SQ*BB*NG];  // forward input-gate proj  128 MB
__device__ float g_gb[BB*NG];             // backward first-step gates
__device__ float g_hf[BB*HH];             // final forward h
__device__ float g_hb[BB*HH];             // backward first-step h

typedef unsigned long long ull;

__device__ __forceinline__ void fma2(ull& d, ull a, ull b) {
    asm("fma.rn.f32x2 %0, %1, %2, %0;" : "+l"(d) : "l"(a), "l"(b));
}
__device__ __forceinline__ ull pk(float x, float y) {
    float2 f = make_float2(x, y); ull v; memcpy(&v, &f, 8); return v;
}
__device__ __forceinline__ float2 unpk(ull v) {
    float2 f; memcpy(&f, &v, 8); return f;
}
__device__ __forceinline__ float sigf(float x)  { return 1.f/(1.f+__expf(-x)); }
__device__ __forceinline__ float tanhf_(float x){ return 1.f - 2.f/(__expf(2.f*x)+1.f); }

// round-to-nearest-even fp32 -> bf16 bits (load-time only)
__device__ __forceinline__ uint32_t bfbits(float x) {
    uint32_t b = __float_as_uint(x);
    return (b + 0x7fffu + ((b >> 16) & 1u)) >> 16;
}
__device__ __forceinline__ uint32_t pk16(float a, float b) {
    return (bfbits(b) << 16) | bfbits(a);
}
// two consecutive-k bf16 (lo=k, hi=k+1) -> f32x2 ull {lo: k, hi: k+1}
__device__ __forceinline__ ull bf2ull(uint32_t p) {
    return ((ull)(p & 0xffff0000u) << 32) | (ull)(p << 16);
}

// ---------------- kernel 1: embedding gather ----------------
__global__ void k_embed(const int* __restrict__ seq, const float* __restrict__ emb,
                        float* __restrict__ x)
{
    int row  = blockIdx.x * 4 + (threadIdx.x >> 5);
    int lane = threadIdx.x & 31;
    int idx  = seq[row];
    float4 v;
    if (idx == 0) v = make_float4(0.f, 0.f, 0.f, 0.f);
    else          v = ((const float4*)emb)[(size_t)idx * 32 + lane];
    ((float4*)x)[(size_t)row * 32 + lane] = v;
}

// ---------------- kernel 2a: big GEMM, 128x128 tiles, 8x8 micro, f32x2 ----------------
__global__ void __launch_bounds__(256)
k_gemm128(const float* __restrict__ A, const float* __restrict__ W,
          const float* __restrict__ bias, float* __restrict__ C)
{
    extern __shared__ float sm[];
    float* As = sm;              // [128 k][132]
    float* Bs = sm + 128*132;    // [128 k][132]

    const int tid = threadIdx.x;
    const int gm0 = blockIdx.y * 128;
    const int gn0 = blockIdx.x * 128;

#pragma unroll
    for (int i = 0; i < 16; ++i) {
        int e   = tid + i * 256;
        int row = e >> 5;
        int kq  = e & 31;
        float4 a = ((const float4*)A)[(size_t)(gm0 + row) * 32 + kq];
        As[(4*kq+0)*132 + row] = a.x;
        As[(4*kq+1)*132 + row] = a.y;
        As[(4*kq+2)*132 + row] = a.z;
        As[(4*kq+3)*132 + row] = a.w;
        float4 w = ((const float4*)W)[(size_t)(gn0 + row) * 32 + kq];
        Bs[(4*kq+0)*132 + row] = w.x;
        Bs[(4*kq+1)*132 + row] = w.y;
        Bs[(4*kq+2)*132 + row] = w.z;
        Bs[(4*kq+3)*132 + row] = w.w;
    }
    __syncthreads();

    const int tx = tid & 15, ty = tid >> 4;
    const int m0 = ty * 8, n0 = tx * 8;

    ull acc[8][4];
#pragma unroll
    for (int j = 0; j < 4; ++j) {
        ull bz = pk(bias[gn0+n0+2*j], bias[gn0+n0+2*j+1]);
#pragma unroll
        for (int i = 0; i < 8; ++i) acc[i][j] = bz;
    }

#pragma unroll 2
    for (int k = 0; k < 128; ++k) {
        float4 aA = *(const float4*)&As[k*132 + m0];
        float4 aB = *(const float4*)&As[k*132 + m0 + 4];
        ulonglong2 b0 = *(const ulonglong2*)&Bs[k*132 + n0];
        ulonglong2 b1 = *(const ulonglong2*)&Bs[k*132 + n0 + 4];
        float av[8] = {aA.x, aA.y, aA.z, aA.w, aB.x, aB.y, aB.z, aB.w};
#pragma unroll
        for (int i = 0; i < 8; ++i) {
            ull ad = pk(av[i], av[i]);
            fma2(acc[i][0], ad, b0.x); fma2(acc[i][1], ad, b0.y);
            fma2(acc[i][2], ad, b1.x); fma2(acc[i][3], ad, b1.y);
        }
    }

#pragma unroll
    for (int i = 0; i < 8; ++i) {
        float2 p0 = unpk(acc[i][0]), p1 = unpk(acc[i][1]);
        float2 p2 = unpk(acc[i][2]), p3 = unpk(acc[i][3]);
        size_t base = (size_t)(gm0 + m0 + i) * 256 + ((gn0 + n0) >> 2);
        ((float4*)C)[base + 0] = make_float4(p0.x, p0.y, p1.x, p1.y);
        ((float4*)C)[base + 1] = make_float4(p2.x, p2.y, p3.x, p3.y);
    }
}

// ---------------- kernel 2b: small GEMM (M=64), 64x64 tiles (proven) ----------------
__global__ void __launch_bounds__(256)
k_gemm(const float* __restrict__ A, const float* __restrict__ W,
       const float* __restrict__ bias, float* __restrict__ C)
{
    extern __shared__ float sm[];
    float* As = sm;             // [128][68]
    float* Bs = sm + 128*68;    // [128][68]

    const int tid = threadIdx.x;
    const int gm0 = blockIdx.y * 64;
    const int gn0 = blockIdx.x * 64;

#pragma unroll
    for (int i = 0; i < 8; ++i) {
        int e   = tid + i * 256;
        int row = e >> 5;
        int kq  = e & 31;
        float4 a = ((const float4*)A)[(size_t)(gm0 + row) * 32 + kq];
        As[(4*kq+0)*68 + row] = a.x;
        As[(4*kq+1)*68 + row] = a.y;
        As[(4*kq+2)*68 + row] = a.z;
        As[(4*kq+3)*68 + row] = a.w;
        float4 w = ((const float4*)W)[(size_t)(gn0 + row) * 32 + kq];
        Bs[(4*kq+0)*68 + row] = w.x;
        Bs[(4*kq+1)*68 + row] = w.y;
        Bs[(4*kq+2)*68 + row] = w.z;
        Bs[(4*kq+3)*68 + row] = w.w;
    }
    __syncthreads();

    const int tx = tid & 15, ty = tid >> 4;
    const int m0 = ty * 4, n0 = tx * 4;

    float b0 = bias[gn0+n0+0], b1 = bias[gn0+n0+1];
    float b2 = bias[gn0+n0+2], b3 = bias[gn0+n0+3];
    ull acc[4][2];
#pragma unroll
    for (int i = 0; i < 4; ++i) { acc[i][0] = pk(b0,b1); acc[i][1] = pk(b2,b3); }

#pragma unroll 4
    for (int k = 0; k < 128; ++k) {
        float4 a4 = *(const float4*)&As[k*68 + m0];
        ulonglong2 bb = *(const ulonglong2*)&Bs[k*68 + n0];
        ull ad;
        ad = pk(a4.x, a4.x); fma2(acc[0][0], ad, bb.x); fma2(acc[0][1], ad, bb.y);
        ad = pk(a4.y, a4.y); fma2(acc[1][0], ad, bb.x); fma2(acc[1][1], ad, bb.y);
        ad = pk(a4.z, a4.z); fma2(acc[2][0], ad, bb.x); fma2(acc[2][1], ad, bb.y);
        ad = pk(a4.w, a4.w); fma2(acc[3][0], ad, bb.x); fma2(acc[3][1], ad, bb.y);
    }

#pragma unroll
    for (int i = 0; i < 4; ++i) {
        float2 lo = unpk(acc[i][0]), hi = unpk(acc[i][1]);
        float4 o = make_float4(lo.x, lo.y, hi.x, hi.y);
        ((float4*)C)[(size_t)(gm0 + m0 + i) * 256 + ((gn0 + n0) >> 2)] = o;
    }
}

// ---------------- kernel 3: forward LSTM scan ----------------
// 32 clusters x 2 CTAs (csz=2: per-step cluster overhead scales with csz),
// 512 thr. Cluster = 2 batch; CTA = 128 hidden units (512 gate rows, ALL
// four gates, full k=256). All weights bf16: i-gate packed in regs
// (32 regs), f/g/o packed in SMEM (192KB). Unpack = 2 ALU ops/pair on the
// idle ALU pipe. Thread = (unit u = tid>>2 in 0..127, kq = tid&3: 64 k's).
// Butterfly over kq -> all 8 (gate,batch) sums in every lane; lane runs
// phase-2 for batch kq&1. Exchange: shfl-gather; lanes 0-3 push v4 to the
// ONE peer, lanes 4-7 mirror locally. Split barrier.cluster.
//
// Dyn smem (floats): whA 32768 (f,g uint4) | whB 16384 (o uint2)
//                    | hbuf[2 buf][2 b][4 seg][68] 2176
__global__ void __cluster_dims__(2,1,1) __launch_bounds__(512,1)
k_scan(const float* __restrict__ xg, const float* __restrict__ Whh,
       float* __restrict__ hout)
{
    extern __shared__ float sm[];
    uint4* whA  = (uint4*)sm;                // [16 c][512 tid]  f,g
    uint2* whB  = (uint2*)(sm + 32768);      // [16 c][512 tid]  o
    float* hbuf = sm + 49152;                // 2176 floats

    const int tid  = threadIdx.x;
    const int rank = blockIdx.x & 1;
    const int bg   = blockIdx.x >> 1;        // 0..31 (2 batch elems each)
    const int u    = tid >> 2;               // local unit 0..127
    const int kq   = tid & 3;                // k in [64*kq, 64*kq+64)
    const int gu   = rank * 128 + u;         // global unit
    const int w    = tid >> 5;               // warp 0..15 (units w*8..w*8+7)
    const int L    = tid & 31;
    const int pb   = kq & 1;                 // phase-2 batch

    // ---- weights: i packed bf16 in regs; f,g,o packed bf16 in smem ----
    uint32_t wi[32];
    {
        const float4* pi = (const float4*)(Whh + (size_t)(0*HH + gu)*HH + kq*64);
        const float4* pf = (const float4*)(Whh + (size_t)(1*HH + gu)*HH + kq*64);
        const float4* pg = (const float4*)(Whh + (size_t)(2*HH + gu)*HH + kq*64);
        const float4* po = (const float4*)(Whh + (size_t)(3*HH + gu)*HH + kq*64);
#pragma unroll
        for (int c = 0; c < 16; ++c) {
            float4 a = pi[c];
            wi[2*c] = pk16(a.x, a.y); wi[2*c+1] = pk16(a.z, a.w);
            float4 f = pf[c], g = pg[c], o = po[c];
            uint4 v;
            v.x = pk16(f.x, f.y); v.y = pk16(f.z, f.w);
            v.z = pk16(g.x, g.y); v.w = pk16(g.z, g.w);
            whA[c*512 + tid] = v;
            uint2 v2;
            v2.x = pk16(o.x, o.y); v2.y = pk16(o.z, o.w);
            whB[c*512 + tid] = v2;
        }
    }
    for (int i = tid; i < 2176; i += 512) hbuf[i] = 0.f;

    float creg = 0.f;

    // ---- exchange setup ----
    // pushing lanes 0-3 (remote to peer), 4-7 (local mirror):
    //   batch bp = L&1, unit-quad hh = (L>>1)&1 -> units w*8 + hh*4 .. +3
    const int bp  = L & 1;
    const int hh  = (L >> 1) & 1;
    const int pgu = rank*128 + w*8 + hh*4;   // global unit base of the quad
    const uint32_t offq = (uint32_t)((bp*272 + (pgu >> 6)*68 + (pgu & 63)) * 4);
    uint32_t pa0 = 0, pa1 = 0;               // remote addrs, buf 0/1
    {
        uint32_t hb32 = (uint32_t)__cvta_generic_to_shared(hbuf);
        asm("mapa.shared::cluster.u32 %0, %1, %2;" : "=r"(pa0) : "r"(hb32 + offq),        "r"(rank ^ 1));
        asm("mapa.shared::cluster.u32 %0, %1, %2;" : "=r"(pa1) : "r"(hb32 + offq + 2176u), "r"(rank ^ 1));
    }
    float* lp0 = hbuf + (bp*272 + (pgu >> 6)*68 + (pgu & 63));  // local mirror
    float* lp1 = lp0 + 544;
    // gather src: h(unit w*8 + hh*4 + i, batch bp) lives at in-warp lane 16*hh + 4*i + bp
    const int gsrc = hh * 16 + bp;

    // xg: lane kq folds gate kq for both batches, unit gu
    const float* xp0 = xg + (size_t)(2*bg + 0) * NG + kq*HH + gu;
    const float* xp1 = xg + (size_t)(2*bg + 1) * NG + kq*HH + gu;
    float nx0 = xp0[0], nx1 = xp1[0];

    __syncthreads();
    asm volatile("barrier.cluster.arrive.aligned;" ::: "memory");
    asm volatile("barrier.cluster.wait.aligned;"   ::: "memory");

#pragma unroll 1
    for (int t = 0; t < SQ; ++t) {
        if (t) asm volatile("barrier.cluster.wait.aligned;" ::: "memory");

        const float* hq0 = hbuf + (t & 1) * 544 + kq * 68;   // batch 0, seg kq
        const float* hq1 = hq0 + 272;                        // batch 1

        ull ai0=0,ai1=0, af0=0,af1=0, ag0=0,ag1=0, ao0=0,ao1=0;
#pragma unroll
        for (int c = 0; c < 16; ++c) {
            ulonglong2 h0 = *(const ulonglong2*)(hq0 + 4*c);
            ulonglong2 h1 = *(const ulonglong2*)(hq1 + 4*c);
            uint4 vfg = whA[c*512 + tid];
            uint2 vo  = whB[c*512 + tid];
            ull ia = bf2ull(wi[2*c]), ib = bf2ull(wi[2*c+1]);
            ull fa = bf2ull(vfg.x),   fb = bf2ull(vfg.y);
            ull ga = bf2ull(vfg.z),   gb = bf2ull(vfg.w);
            ull oa = bf2ull(vo.x),    ob = bf2ull(vo.y);
            fma2(ai0, ia, h0.x); fma2(ai0, ib, h0.y);
            fma2(ai1, ia, h1.x); fma2(ai1, ib, h1.y);
            fma2(af0, fa, h0.x); fma2(af0, fb, h0.y);
            fma2(af1, fa, h1.x); fma2(af1, fb, h1.y);
            fma2(ag0, ga, h0.x); fma2(ag0, gb, h0.y);
            fma2(ag1, ga, h1.x); fma2(ag1, gb, h1.y);
            fma2(ao0, oa, h0.x); fma2(ao0, ob, h0.y);
            fma2(ao1, oa, h1.x); fma2(ao1, ob, h1.y);
        }

        // pairwise collapse + fold xg (lane kq owns gate kq, both batches)
        float2 f;
        f = unpk(ai0); float si0 = f.x + f.y;
        f = unpk(ai1); float si1 = f.x + f.y;
        f = unpk(af0); float sf0 = f.x + f.y;
        f = unpk(af1); float sf1 = f.x + f.y;
        f = unpk(ag0); float sg0 = f.x + f.y;
        f = unpk(ag1); float sg1 = f.x + f.y;
        f = unpk(ao0); float so0 = f.x + f.y;
        f = unpk(ao1); float so1 = f.x + f.y;
        if      (kq == 0) { si0 += nx0; si1 += nx1; }
        else if (kq == 1) { sf0 += nx0; sf1 += nx1; }
        else if (kq == 2) { sg0 += nx0; sg1 += nx1; }
        else              { so0 += nx0; so1 += nx1; }

        // butterfly over kq (lane bits 0-1): all lanes get all 8 full sums
        si0 += __shfl_xor_sync(~0u, si0, 1); si0 += __shfl_xor_sync(~0u, si0, 2);
        si1 += __shfl_xor_sync(~0u, si1, 1); si1 += __shfl_xor_sync(~0u, si1, 2);
        sf0 += __shfl_xor_sync(~0u, sf0, 1); sf0 += __shfl_xor_sync(~0u, sf0, 2);
        sf1 += __shfl_xor_sync(~0u, sf1, 1); sf1 += __shfl_xor_sync(~0u, sf1, 2);
        sg0 += __shfl_xor_sync(~0u, sg0, 1); sg0 += __shfl_xor_sync(~0u, sg0, 2);
        sg1 += __shfl_xor_sync(~0u, sg1, 1); sg1 += __shfl_xor_sync(~0u, sg1, 2);
        so0 += __shfl_xor_sync(~0u, so0, 1); so0 += __shfl_xor_sync(~0u, so0, 2);
        so1 += __shfl_xor_sync(~0u, so1, 1); so1 += __shfl_xor_sync(~0u, so1, 2);

        // phase 2 (2 redundant copies per (unit,batch)), batch pb = kq&1
        float gi = pb ? si1 : si0;
        float gf = pb ? sf1 : sf0;
        float gg = pb ? sg1 : sg0;
        float go = pb ? so1 : so0;
        float iv = sigf(gi), fv = sigf(gf), cv = tanhf_(gg), ov = sigf(go);
        creg = fv * creg + iv * cv;
        float hv = ov * tanhf_(creg);

        if (t < SQ - 1) {
            // gather the quad's h (batch bp) into every lane's v0..v3
            float v0 = __shfl_sync(~0u, hv, gsrc);
            float v1 = __shfl_sync(~0u, hv, gsrc + 4);
            float v2 = __shfl_sync(~0u, hv, gsrc + 8);
            float v3 = __shfl_sync(~0u, hv, gsrc + 12);
            const bool b1 = ((t & 1) == 0);            // write buffer (t+1)&1
            if (L < 4) {
                uint32_t a = b1 ? pa1 : pa0;
                asm volatile("st.shared::cluster.v4.f32 [%0], {%1, %2, %3, %4};"
                             :: "r"(a), "f"(v0), "f"(v1), "f"(v2), "f"(v3) : "memory");
            } else if (L < 8) {
                float* lp = b1 ? lp1 : lp0;
                *(float4*)lp = make_float4(v0, v1, v2, v3);
            }
            asm volatile("barrier.cluster.arrive.aligned;" ::: "memory");
            // prefetch next xg in the barrier's shadow
            nx0 = xp0[(size_t)(t + 1) * (BB * NG)];
            nx1 = xp1[(size_t)(t + 1) * (BB * NG)];
        } else {
            if (kq < 2)
                hout[(size_t)(2*bg + pb) * HH + gu] = hv;
        }
    }
}

// ---------------- kernel 4: backward first-step (h0=c0=0) ----------------
__global__ void k_hback(const float* __restrict__ gb, float* __restrict__ hb)
{
    int i = blockIdx.x * 256 + threadIdx.x;
    int b = i >> 8, j = i & 255;
    const float* g = gb + (size_t)b * NG;
    float iv = sigf(g[j]);
    float gv = tanhf_(g[512 + j]);
    float ov = sigf(g[768 + j]);
    float c  = iv * gv;
    hb[i] = ov * tanhf_(c);
}

// ---------------- kernel 5: output head (warp per batch elem) ----------------
__global__ void k_out(const float* __restrict__ hf, const float* __restrict__ hb,
                      const float* __restrict__ Wout, const float* __restrict__ bout,
                      float* __restrict__ out)
{
    int b = blockIdx.x, lane = threadIdx.x;
    const float4* hf4 = (const float4*)(hf + (size_t)b * HH);
    const float4* hb4 = (const float4*)(hb + (size_t)b * HH);
    const float4* wA  = (const float4*)Wout;
    const float4* wB  = (const float4*)(Wout + HH);
    float acc = 0.f;
#pragma unroll
    for (int i = 0; i < 2; ++i) {
        int idx = lane + 32*i;
        float4 a = hf4[idx], w = wA[idx];
        acc += a.x*w.x + a.y*w.y + a.z*w.z + a.w*w.w;
        float4 c = hb4[idx], v = wB[idx];
        acc += c.x*v.x + c.y*v.y + c.z*v.z + c.w*v.w;
    }
#pragma unroll
    for (int o = 16; o; o >>= 1) acc += __shfl_xor_sync(~0u, acc, o);
    if (lane == 0) out[b] = sigf(acc + bout[0]);
}

// ---------------- launch ----------------
extern "C" void kernel_launch(void* const* d_in, const int* in_sizes, int n_in,
                              void* d_out, int out_size)
{
    (void)in_sizes; (void)n_in; (void)out_size;
    const int*   seq  = (const int*)  d_in[0];
    const float* emb  = (const float*)d_in[1];
    const float* Wihf = (const float*)d_in[2];
    const float* Whhf = (const float*)d_in[3];
    const float* bf   = (const float*)d_in[4];
    const float* Wihb = (const float*)d_in[5];
    const float* Whhb = (const float*)d_in[6];
    const float* bb   = (const float*)d_in[7];
    const float* Wout = (const float*)d_in[8];
    const float* bout = (const float*)d_in[9];
    (void)Whhb;
    float* out = (float*)d_out;

    float *x, *xgf, *gb, *hf, *hb;
    cudaGetSymbolAddress((void**)&x,   g_x);
    cudaGetSymbolAddress((void**)&xgf, g_xg);
    cudaGetSymbolAddress((void**)&gb,  g_gb);
    cudaGetSymbolAddress((void**)&hf,  g_hf);
    cudaGetSymbolAddress((void**)&hb,  g_hb);

    const int SMEM_GEMM  = 2 * 128 * 68 * 4;                 // 69632
    const int SMEM_G128  = 2 * 128 * 132 * 4;                // 135168
    const int SMEM_SCAN  = (49152 + 2176) * 4;               // 205312
    cudaFuncSetAttribute(k_gemm,    cudaFuncAttributeMaxDynamicSharedMemorySize, SMEM_GEMM);
    cudaFuncSetAttribute(k_gemm128, cudaFuncAttributeMaxDynamicSharedMemorySize, SMEM_G128);
    cudaFuncSetAttribute(k_scan,    cudaFuncAttributeMaxDynamicSharedMemorySize, SMEM_SCAN);

    k_embed<<<SQ*BB/4, 128>>>(seq, emb, x);
    dim3 g2(8, SQ*BB/128);
    k_gemm128<<<g2, 256, SMEM_G128>>>(x, Wihf, bf, xgf);
    dim3 g2b(16, 1);
    k_gemm<<<g2b, 256, SMEM_GEMM>>>(x + (size_t)(SQ-1)*BB*EE, Wihb, bb, gb);
    k_scan<<<64, 512, SMEM_SCAN>>>(xgf, Whhf, hf);
    k_hback<<<64, 256>>>(gb, hb);
    k_out<<<64, 32>>>(hf, hb, Wout, bout, out);
}

// round 16
// speedup vs baseline: 1.2817x; 1.2817x over previous
#include <cuda_runtime.h>
#include <cstdint>
#include <cstring>

#define SQ 512
#define BB 64
#define EE 128
#define HH 256
#define NG 1024   // 4*H

// ---------------- scratch (static device memory; no allocations) ----------------
__device__ float g_x [SQ*BB*EE];          // embedded inputs          16 MB
__device__ float g_xg[(size_t)SQ*BB*NG];  // forward input-gate proj  128 MB
__device__ float g_gb[BB*NG];             // backward first-step gates
__device__ float g_hf[BB*HH];             // final forward h
__device__ float g_hb[BB*HH];             // backward first-step h

typedef unsigned long long ull;

__device__ __forceinline__ void fma2(ull& d, ull a, ull b) {
    asm("fma.rn.f32x2 %0, %1, %2, %0;" : "+l"(d) : "l"(a), "l"(b));
}
__device__ __forceinline__ ull pk(float x, float y) {
    float2 f = make_float2(x, y); ull v; memcpy(&v, &f, 8); return v;
}
__device__ __forceinline__ float2 unpk(ull v) {
    float2 f; memcpy(&f, &v, 8); return f;
}
__device__ __forceinline__ float sigf(float x)  { return 1.f/(1.f+__expf(-x)); }
__device__ __forceinline__ float tanhf_(float x){ return 1.f - 2.f/(__expf(2.f*x)+1.f); }

// round-to-nearest-even fp32 -> bf16 bits (load-time only)
__device__ __forceinline__ uint32_t bfbits(float x) {
    uint32_t b = __float_as_uint(x);
    return (b + 0x7fffu + ((b >> 16) & 1u)) >> 16;
}
__device__ __forceinline__ uint32_t pk16(float a, float b) {
    return (bfbits(b) << 16) | bfbits(a);
}
// two consecutive-k bf16 -> f32x2 ull (2 ALU ops: lo = p<<16, hi = p&0xffff0000)
__device__ __forceinline__ ull bf2ull(uint32_t p) {
    return ((ull)(p & 0xffff0000u) << 32) | (ull)(p << 16);
}

// ---------------- kernel 1: embedding gather ----------------
__global__ void k_embed(const int* __restrict__ seq, const float* __restrict__ emb,
                        float* __restrict__ x)
{
    int row  = blockIdx.x * 4 + (threadIdx.x >> 5);
    int lane = threadIdx.x & 31;
    int idx  = seq[row];
    float4 v;
    if (idx == 0) v = make_float4(0.f, 0.f, 0.f, 0.f);
    else          v = ((const float4*)emb)[(size_t)idx * 32 + lane];
    ((float4*)x)[(size_t)row * 32 + lane] = v;
}

// ---------------- kernel 2a: big GEMM, 128x128 tiles, 8x8 micro, f32x2 ----------------
__global__ void __launch_bounds__(256)
k_gemm128(const float* __restrict__ A, const float* __restrict__ W,
          const float* __restrict__ bias, float* __restrict__ C)
{
    extern __shared__ float sm[];
    float* As = sm;              // [128 k][132]
    float* Bs = sm + 128*132;    // [128 k][132]

    const int tid = threadIdx.x;
    const int gm0 = blockIdx.y * 128;
    const int gn0 = blockIdx.x * 128;

#pragma unroll
    for (int i = 0; i < 16; ++i) {
        int e   = tid + i * 256;
        int row = e >> 5;
        int kq  = e & 31;
        float4 a = ((const float4*)A)[(size_t)(gm0 + row) * 32 + kq];
        As[(4*kq+0)*132 + row] = a.x;
        As[(4*kq+1)*132 + row] = a.y;
        As[(4*kq+2)*132 + row] = a.z;
        As[(4*kq+3)*132 + row] = a.w;
        float4 w = ((const float4*)W)[(size_t)(gn0 + row) * 32 + kq];
        Bs[(4*kq+0)*132 + row] = w.x;
        Bs[(4*kq+1)*132 + row] = w.y;
        Bs[(4*kq+2)*132 + row] = w.z;
        Bs[(4*kq+3)*132 + row] = w.w;
    }
    __syncthreads();

    const int tx = tid & 15, ty = tid >> 4;
    const int m0 = ty * 8, n0 = tx * 8;

    ull acc[8][4];
#pragma unroll
    for (int j = 0; j < 4; ++j) {
        ull bz = pk(bias[gn0+n0+2*j], bias[gn0+n0+2*j+1]);
#pragma unroll
        for (int i = 0; i < 8; ++i) acc[i][j] = bz;
    }

#pragma unroll 2
    for (int k = 0; k < 128; ++k) {
        float4 aA = *(const float4*)&As[k*132 + m0];
        float4 aB = *(const float4*)&As[k*132 + m0 + 4];
        ulonglong2 b0 = *(const ulonglong2*)&Bs[k*132 + n0];
        ulonglong2 b1 = *(const ulonglong2*)&Bs[k*132 + n0 + 4];
        float av[8] = {aA.x, aA.y, aA.z, aA.w, aB.x, aB.y, aB.z, aB.w};
#pragma unroll
        for (int i = 0; i < 8; ++i) {
            ull ad = pk(av[i], av[i]);
            fma2(acc[i][0], ad, b0.x); fma2(acc[i][1], ad, b0.y);
            fma2(acc[i][2], ad, b1.x); fma2(acc[i][3], ad, b1.y);
        }
    }

#pragma unroll
    for (int i = 0; i < 8; ++i) {
        float2 p0 = unpk(acc[i][0]), p1 = unpk(acc[i][1]);
        float2 p2 = unpk(acc[i][2]), p3 = unpk(acc[i][3]);
        size_t base = (size_t)(gm0 + m0 + i) * 256 + ((gn0 + n0) >> 2);
        ((float4*)C)[base + 0] = make_float4(p0.x, p0.y, p1.x, p1.y);
        ((float4*)C)[base + 1] = make_float4(p2.x, p2.y, p3.x, p3.y);
    }
}

// ---------------- kernel 2b: small GEMM (M=64), 64x64 tiles (proven) ----------------
__global__ void __launch_bounds__(256)
k_gemm(const float* __restrict__ A, const float* __restrict__ W,
       const float* __restrict__ bias, float* __restrict__ C)
{
    extern __shared__ float sm[];
    float* As = sm;             // [128][68]
    float* Bs = sm + 128*68;    // [128][68]

    const int tid = threadIdx.x;
    const int gm0 = blockIdx.y * 64;
    const int gn0 = blockIdx.x * 64;

#pragma unroll
    for (int i = 0; i < 8; ++i) {
        int e   = tid + i * 256;
        int row = e >> 5;
        int kq  = e & 31;
        float4 a = ((const float4*)A)[(size_t)(gm0 + row) * 32 + kq];
        As[(4*kq+0)*68 + row] = a.x;
        As[(4*kq+1)*68 + row] = a.y;
        As[(4*kq+2)*68 + row] = a.z;
        As[(4*kq+3)*68 + row] = a.w;
        float4 w = ((const float4*)W)[(size_t)(gn0 + row) * 32 + kq];
        Bs[(4*kq+0)*68 + row] = w.x;
        Bs[(4*kq+1)*68 + row] = w.y;
        Bs[(4*kq+2)*68 + row] = w.z;
        Bs[(4*kq+3)*68 + row] = w.w;
    }
    __syncthreads();

    const int tx = tid & 15, ty = tid >> 4;
    const int m0 = ty * 4, n0 = tx * 4;

    float b0 = bias[gn0+n0+0], b1 = bias[gn0+n0+1];
    float b2 = bias[gn0+n0+2], b3 = bias[gn0+n0+3];
    ull acc[4][2];
#pragma unroll
    for (int i = 0; i < 4; ++i) { acc[i][0] = pk(b0,b1); acc[i][1] = pk(b2,b3); }

#pragma unroll 4
    for (int k = 0; k < 128; ++k) {
        float4 a4 = *(const float4*)&As[k*68 + m0];
        ulonglong2 bb = *(const ulonglong2*)&Bs[k*68 + n0];
        ull ad;
        ad = pk(a4.x, a4.x); fma2(acc[0][0], ad, bb.x); fma2(acc[0][1], ad, bb.y);
        ad = pk(a4.y, a4.y); fma2(acc[1][0], ad, bb.x); fma2(acc[1][1], ad, bb.y);
        ad = pk(a4.z, a4.z); fma2(acc[2][0], ad, bb.x); fma2(acc[2][1], ad, bb.y);
        ad = pk(a4.w, a4.w); fma2(acc[3][0], ad, bb.x); fma2(acc[3][1], ad, bb.y);
    }

#pragma unroll
    for (int i = 0; i < 4; ++i) {
        float2 lo = unpk(acc[i][0]), hi = unpk(acc[i][1]);
        float4 o = make_float4(lo.x, lo.y, hi.x, hi.y);
        ((float4*)C)[(size_t)(gm0 + m0 + i) * 256 + ((gn0 + n0) >> 2)] = o;
    }
}

// ---------------- kernel 3: forward LSTM scan ----------------
// R14 base (csz=4, 512 thr, 32 clusters, 2 batch/cluster, CTA = 64 units).
// Changes vs R14:
//  (1) loop sync: barrier.cluster -> per-source double-buffered mbarriers fed
//      by st.async.mbarrier::complete_tx (pipelined generations, no release
//      fence/flush, no arrive contention); only threads 0-3 wait (HW-sleep
//      try_wait), __syncthreads releases the CTA.
//  (2) weights: i,f,g bf16-packed in 48 registers; only o streams from SMEM.
//
// Dyn smem (floats): who uint2[8c][512] = 8192 | hbuf[2][2 b][8 seg][36] 1152
//                    | 8 mbars (mb[buf][src]) = 16
__global__ void __cluster_dims__(4,1,1) __launch_bounds__(512,1)
k_scan(const float* __restrict__ xg, const float* __restrict__ Whh,
       float* __restrict__ hout)
{
    extern __shared__ float sm[];
    uint2* who  = (uint2*)sm;            // [8 c][512 tid]  o-gate bf16 pairs
    float* hbuf = sm + 8192;             // 1152 floats

    const int tid   = threadIdx.x;
    const int rank  = blockIdx.x & 3;
    const int bg    = blockIdx.x >> 2;        // 0..31  (2 batch elems each)
    const int jbase = rank << 6;              // 64-unit hidden slice

    const int u  = tid >> 3;                  // hidden unit 0..63
    const int ko = tid & 7;                   // k in [32*ko, 32*ko+32)
    const int pb = ko & 1;                    // phase-2 batch
    const int dr = ko >> 1;                   // xg gate for this lane
    const int w  = tid >> 5;                  // warp 0..15 (units w*4..w*4+3)
    const int L  = tid & 31;

    const uint32_t smbase = (uint32_t)__cvta_generic_to_shared(sm);
    const uint32_t hb32   = smbase + 8192u * 4u;
    const uint32_t mb32   = smbase + 9344u * 4u;   // 8 x u64 mbars

    // init + arm both phases' mbars (same thread: init then arrive.expect_tx)
    if (tid < 8) {
        uint32_t a = mb32 + (uint32_t)tid * 8u;
        asm volatile("mbarrier.init.shared.b64 [%0], 1;" :: "r"(a) : "memory");
        asm volatile("mbarrier.arrive.expect_tx.shared.b64 _, [%0], %1;"
                     :: "r"(a), "r"(512u) : "memory");
    }

    // ---- weights: i,f,g packed bf16 in regs; o packed bf16 in smem ----
    uint32_t wi[16], wf[16], wg[16];
    {
        const float4* pi = (const float4*)(Whh + (size_t)(0*HH + jbase + u)*HH + ko*32);
        const float4* pf = (const float4*)(Whh + (size_t)(1*HH + jbase + u)*HH + ko*32);
        const float4* pg = (const float4*)(Whh + (size_t)(2*HH + jbase + u)*HH + ko*32);
        const float4* po = (const float4*)(Whh + (size_t)(3*HH + jbase + u)*HH + ko*32);
#pragma unroll
        for (int c = 0; c < 8; ++c) {
            float4 a = pi[c]; wi[2*c] = pk16(a.x, a.y); wi[2*c+1] = pk16(a.z, a.w);
            float4 b = pf[c]; wf[2*c] = pk16(b.x, b.y); wf[2*c+1] = pk16(b.z, b.w);
            float4 g = pg[c]; wg[2*c] = pk16(g.x, g.y); wg[2*c+1] = pk16(g.z, g.w);
            float4 o = po[c];
            uint2 v; v.x = pk16(o.x, o.y); v.y = pk16(o.z, o.w);
            who[c*512 + tid] = v;
        }
    }
    for (int i = tid; i < 1152; i += 512) hbuf[i] = 0.f;

    float creg = 0.f;

    // push setup (lanes 0-7 per warp): lane l -> (batch l&1, dest rank l>>1),
    // quad units jbase + w*4 .. +3; data + remote mbar addrs for both buffers
    uint32_t pa0 = 0, pa1 = 0, ma0 = 0, ma1 = 0;
    if (L < 8) {
        int ppb = L & 1;
        int pdr = L >> 1;
        int k0  = jbase + w * 4;
        uint32_t o0 = (uint32_t)(((0*2 + ppb)*288 + (k0>>5)*36 + (k0&31)) * 4);
        uint32_t o1 = o0 + 576u * 4u;
        asm("mapa.shared::cluster.u32 %0, %1, %2;" : "=r"(pa0) : "r"(hb32 + o0), "r"(pdr));
        asm("mapa.shared::cluster.u32 %0, %1, %2;" : "=r"(pa1) : "r"(hb32 + o1), "r"(pdr));
        asm("mapa.shared::cluster.u32 %0, %1, %2;" : "=r"(ma0) : "r"(mb32 + (uint32_t)((0*4 + rank) * 8)), "r"(pdr));
        asm("mapa.shared::cluster.u32 %0, %1, %2;" : "=r"(ma1) : "r"(mb32 + (uint32_t)((1*4 + rank) * 8)), "r"(pdr));
    }
    const int gsrc = L & 1;   // gather source lane offset (batch of pusher)

    // xg: lane ko loads gate dr, batch pb, for unit u
    const float* xp = xg + (size_t)(2*bg + pb) * NG + dr*HH + jbase + u;
    float nx = xp[0];

    __syncthreads();
    asm volatile("barrier.cluster.arrive.aligned;" ::: "memory");
    asm volatile("barrier.cluster.wait.aligned;"   ::: "memory");

    int ph0 = 0, ph1 = 0;   // phase parity per buffer

#pragma unroll 1
    for (int t = 0; t < SQ; ++t) {
        if (t) {
            const int b = t & 1;
            if (tid < 4) {
                uint32_t wa  = mb32 + (uint32_t)((b*4 + tid) * 8);
                uint32_t par = (uint32_t)(b ? ph1 : ph0);
                asm volatile(
                    "{\n\t.reg .pred P;\n"
                    "WLP%=:\n\t"
                    "mbarrier.try_wait.parity.acquire.cluster.shared::cta.b64 P, [%0], %1, 0x989680;\n\t"
                    "@!P bra WLP%=;\n\t}"
                    :: "r"(wa), "r"(par) : "memory");
                // re-arm for the next phase of this mbar
                asm volatile("mbarrier.arrive.expect_tx.shared.b64 _, [%0], %1;"
                             :: "r"(wa), "r"(512u) : "memory");
            }
            __syncthreads();
            if (b) ph1 ^= 1; else ph0 ^= 1;
        }

        const float* hq = hbuf + (t & 1) * 576 + ko * 36;

        ull ai0=0,ai1=0, af0=0,af1=0, ag0=0,ag1=0, ao0=0,ao1=0;
#pragma unroll
        for (int c = 0; c < 8; ++c) {
            ulonglong2 h0 = *(const ulonglong2*)(hq + 4*c);          // batch 0
            ulonglong2 h1 = *(const ulonglong2*)(hq + 288 + 4*c);    // batch 1
            uint2 vo = who[c*512 + tid];
            ull ia = bf2ull(wi[2*c]), ib = bf2ull(wi[2*c+1]);
            ull fa = bf2ull(wf[2*c]), fb = bf2ull(wf[2*c+1]);
            ull ga = bf2ull(wg[2*c]), gb = bf2ull(wg[2*c+1]);
            ull oa = bf2ull(vo.x),    ob = bf2ull(vo.y);
            fma2(ai0, ia, h0.x); fma2(ai0, ib, h0.y);
            fma2(ai1, ia, h1.x); fma2(ai1, ib, h1.y);
            fma2(af0, fa, h0.x); fma2(af0, fb, h0.y);
            fma2(af1, fa, h1.x); fma2(af1, fb, h1.y);
            fma2(ag0, ga, h0.x); fma2(ag0, gb, h0.y);
            fma2(ag1, ga, h1.x); fma2(ag1, gb, h1.y);
            fma2(ao0, oa, h0.x); fma2(ao0, ob, h0.y);
            fma2(ao1, oa, h1.x); fma2(ao1, ob, h1.y);
        }

        // pairwise collapse + fold this lane's xg into its (gate dr, batch pb)
        float2 f;
        f = unpk(ai0); float si0 = f.x + f.y;
        f = unpk(ai1); float si1 = f.x + f.y;
        f = unpk(af0); float sf0 = f.x + f.y;
        f = unpk(af1); float sf1 = f.x + f.y;
        f = unpk(ag0); float sg0 = f.x + f.y;
        f = unpk(ag1); float sg1 = f.x + f.y;
        f = unpk(ao0); float so0 = f.x + f.y;
        f = unpk(ao1); float so1 = f.x + f.y;
        if      (ko == 0) si0 += nx;
        else if (ko == 1) si1 += nx;
        else if (ko == 2) sf0 += nx;
        else if (ko == 3) sf1 += nx;
        else if (ko == 4) sg0 += nx;
        else if (ko == 5) sg1 += nx;
        else if (ko == 6) so0 += nx;
        else              so1 += nx;

        // 3-stage butterfly over ko: all lanes get all 8 full sums
#pragma unroll
        for (int o = 1; o <= 4; o <<= 1) {
            si0 += __shfl_xor_sync(~0u, si0, o);
            si1 += __shfl_xor_sync(~0u, si1, o);
            sf0 += __shfl_xor_sync(~0u, sf0, o);
            sf1 += __shfl_xor_sync(~0u, sf1, o);
            sg0 += __shfl_xor_sync(~0u, sg0, o);
            sg1 += __shfl_xor_sync(~0u, sg1, o);
            so0 += __shfl_xor_sync(~0u, so0, o);
            so1 += __shfl_xor_sync(~0u, so1, o);
        }

        // phase 2 (redundant copies per (unit,batch)), batch pb
        float gi = pb ? si1 : si0;
        float gf = pb ? sf1 : sf0;
        float gg = pb ? sg1 : sg0;
        float go = pb ? so1 : so0;
        float iv = sigf(gi), fv = sigf(gf), cv = tanhf_(gg), ov = sigf(go);
        creg = fv * creg + iv * cv;
        float hv = ov * tanhf_(creg);

        if (t < SQ - 1) {
            // gather 4 units' h (batch gsrc) into lanes 0-7
            float v0 = __shfl_sync(~0u, hv, 0*8 + gsrc);
            float v1 = __shfl_sync(~0u, hv, 1*8 + gsrc);
            float v2 = __shfl_sync(~0u, hv, 2*8 + gsrc);
            float v3 = __shfl_sync(~0u, hv, 3*8 + gsrc);
            if (L < 8) {
                const bool b1 = ((t & 1) == 0);        // write buffer (t+1)&1
                uint32_t a  = b1 ? pa1 : pa0;
                uint32_t ma = b1 ? ma1 : ma0;
                ull q0 = pk(v0, v1), q1 = pk(v2, v3);
                asm volatile("st.async.shared::cluster.mbarrier::complete_tx::bytes.b64 [%0], %1, [%2];"
                             :: "r"(a),      "l"(q0), "r"(ma) : "memory");
                asm volatile("st.async.shared::cluster.mbarrier::complete_tx::bytes.b64 [%0], %1, [%2];"
                             :: "r"(a + 8u), "l"(q1), "r"(ma) : "memory");
            }
            // prefetch next xg (overlaps peers' pushes)
            nx = xp[(size_t)(t + 1) * (BB * NG)];
        } else {
            if (ko < 2)
                hout[(size_t)(2*bg + pb) * HH + jbase + u] = hv;
        }
    }

    // drain before exit
    asm volatile("barrier.cluster.arrive.aligned;" ::: "memory");
    asm volatile("barrier.cluster.wait.aligned;"   ::: "memory");
}

// ---------------- kernel 4: backward first-step (h0=c0=0) ----------------
__global__ void k_hback(const float* __restrict__ gb, float* __restrict__ hb)
{
    int i = blockIdx.x * 256 + threadIdx.x;
    int b = i >> 8, j = i & 255;
    const float* g = gb + (size_t)b * NG;
    float iv = sigf(g[j]);
    float gv = tanhf_(g[512 + j]);
    float ov = sigf(g[768 + j]);
    float c  = iv * gv;
    hb[i] = ov * tanhf_(c);
}

// ---------------- kernel 5: output head (warp per batch elem) ----------------
__global__ void k_out(const float* __restrict__ hf, const float* __restrict__ hb,
                      const float* __restrict__ Wout, const float* __restrict__ bout,
                      float* __restrict__ out)
{
    int b = blockIdx.x, lane = threadIdx.x;
    const float4* hf4 = (const float4*)(hf + (size_t)b * HH);
    const float4* hb4 = (const float4*)(hb + (size_t)b * HH);
    const float4* wA  = (const float4*)Wout;
    const float4* wB  = (const float4*)(Wout + HH);
    float acc = 0.f;
#pragma unroll
    for (int i = 0; i < 2; ++i) {
        int idx = lane + 32*i;
        float4 a = hf4[idx], w = wA[idx];
        acc += a.x*w.x + a.y*w.y + a.z*w.z + a.w*w.w;
        float4 c = hb4[idx], v = wB[idx];
        acc += c.x*v.x + c.y*v.y + c.z*v.z + c.w*v.w;
    }
#pragma unroll
    for (int o = 16; o; o >>= 1) acc += __shfl_xor_sync(~0u, acc, o);
    if (lane == 0) out[b] = sigf(acc + bout[0]);
}

// ---------------- launch ----------------
extern "C" void kernel_launch(void* const* d_in, const int* in_sizes, int n_in,
                              void* d_out, int out_size)
{
    (void)in_sizes; (void)n_in; (void)out_size;
    const int*   seq  = (const int*)  d_in[0];
    const float* emb  = (const float*)d_in[1];
    const float* Wihf = (const float*)d_in[2];
    const float* Whhf = (const float*)d_in[3];
    const float* bf   = (const float*)d_in[4];
    const float* Wihb = (const float*)d_in[5];
    const float* Whhb = (const float*)d_in[6];
    const float* bb   = (const float*)d_in[7];
    const float* Wout = (const float*)d_in[8];
    const float* bout = (const float*)d_in[9];
    (void)Whhb;
    float* out = (float*)d_out;

    float *x, *xgf, *gb, *hf, *hb;
    cudaGetSymbolAddress((void**)&x,   g_x);
    cudaGetSymbolAddress((void**)&xgf, g_xg);
    cudaGetSymbolAddress((void**)&gb,  g_gb);
    cudaGetSymbolAddress((void**)&hf,  g_hf);
    cudaGetSymbolAddress((void**)&hb,  g_hb);

    const int SMEM_GEMM  = 2 * 128 * 68 * 4;                 // 69632
    const int SMEM_G128  = 2 * 128 * 132 * 4;                // 135168
    const int SMEM_SCAN  = (8192 + 1152 + 16) * 4;           // 37440
    cudaFuncSetAttribute(k_gemm,    cudaFuncAttributeMaxDynamicSharedMemorySize, SMEM_GEMM);
    cudaFuncSetAttribute(k_gemm128, cudaFuncAttributeMaxDynamicSharedMemorySize, SMEM_G128);
    cudaFuncSetAttribute(k_scan,    cudaFuncAttributeMaxDynamicSharedMemorySize, SMEM_SCAN);

    k_embed<<<SQ*BB/4, 128>>>(seq, emb, x);
    dim3 g2(8, SQ*BB/128);
    k_gemm128<<<g2, 256, SMEM_G128>>>(x, Wihf, bf, xgf);
    dim3 g2b(16, 1);
    k_gemm<<<g2b, 256, SMEM_GEMM>>>(x + (size_t)(SQ-1)*BB*EE, Wihb, bb, gb);
    k_scan<<<128, 512, SMEM_SCAN>>>(xgf, Whhf, hf);
    k_hback<<<64, 256>>>(gb, hb);
    k_out<<<64, 32>>>(hf, hb, Wout, bout, out);
}